// round 4
// baseline (speedup 1.0000x reference)
#include <cuda_runtime.h>
#include <math.h>

#define BB    128
#define NN    22
#define FF    448
#define HD    64
#define NPAIR 484
#define NUP   231      // i<j
#define NUPD  253      // i<=j
#define PSTR  65       // proj row stride in K2 smem
#define XSS   452      // xs row stride (floats)
#define XQF   1032     // packed-pair row stride (floats)

__device__ float g_proj[4 * BB * NN * HD];
__device__ float g_corr[BB * NPAIR];

__device__ __forceinline__ void fma2b(float2& d, float x0, float x1, float w) {
    float2 a = make_float2(x0, x1);
    float2 b = make_float2(w, w);
    asm("fma.rn.f32x2 %0, %1, %2, %0;"
        : "+l"(*reinterpret_cast<unsigned long long*>(&d))
        : "l"(*reinterpret_cast<const unsigned long long*>(&a)),
          "l"(*reinterpret_cast<const unsigned long long*>(&b)));
}

__device__ __forceinline__ void fma2(float2& d, const float2 a, const float2 b) {
    asm("fma.rn.f32x2 %0, %1, %2, %0;"
        : "+l"(*reinterpret_cast<unsigned long long*>(&d))
        : "l"(*reinterpret_cast<const unsigned long long*>(&a)),
          "l"(*reinterpret_cast<const unsigned long long*>(&b)));
}

__device__ __forceinline__ float warpSum(float v) {
    #pragma unroll
    for (int o = 16; o; o >>= 1) v += __shfl_xor_sync(0xffffffffu, v, o);
    return v;
}

#define PSTEP(A, XV)                                              \
    fma2b(A[0], XV.x, XV.y, w0.x); fma2b(A[0], XV.z, XV.w, w1.x); \
    fma2b(A[1], XV.x, XV.y, w0.y); fma2b(A[1], XV.z, XV.w, w1.y); \
    fma2b(A[2], XV.x, XV.y, w0.z); fma2b(A[2], XV.z, XV.w, w1.z); \
    fma2b(A[3], XV.x, XV.y, w0.w); fma2b(A[3], XV.z, XV.w, w1.w);

// ================= K1: projections (roles 0-3) + stats/gram (roles 4-5) =================
__global__ __launch_bounds__(128)
void k1(const float* __restrict__ x,
        const float* __restrict__ cw1, const float* __restrict__ cb1,
        const float* __restrict__ emb,
        const float* __restrict__ sw1, const float* __restrict__ sb1) {
    extern __shared__ __align__(16) float sm[];
    const int b    = blockIdx.y;
    const int role = blockIdx.x;
    const int tid  = threadIdx.x;
    const int lane = tid & 31;
    const int warp = tid >> 5;

    if (role < 4) {
        // ---- projection GEMM for matrix m = role ----
        const int m = role;
        const float* xb = x + (size_t)b * NN * FF;
        for (int idx = tid; idx < NN * FF; idx += 128) {
            int i = idx / FF, k = idx - i * FF;
            sm[(i >> 1) * XQF + (64 + k) * 2 + (i & 1)] = xb[idx];
        }
        for (int idx = tid; idx < NN * HD; idx += 128) {
            int i = idx >> 6, k = idx & 63;
            sm[(i >> 1) * XQF + k * 2 + (i & 1)] = emb[idx];
        }
        for (int idx = tid; idx < XQF; idx += 128) sm[11 * XQF + idx] = 0.f;  // pad pair
        __syncthreads();

        const int ks = (tid >> 4) & 1;
        const int c0 = (tid & 15) * 4;
        const int rg = (tid >> 5) & 3;
        const int p0 = rg * 3;

        float2 acc[3][4];
        #pragma unroll
        for (int pp = 0; pp < 3; pp++)
            #pragma unroll
            for (int cc = 0; cc < 4; cc++) acc[pp][cc] = make_float2(0.f, 0.f);

        const float* wB;
        if      (m == 0) wB = cw1 + (      ks * 224) * HD + c0;
        else if (m == 1) wB = cw1 + (448 + ks * 224) * HD + c0;
        else if (m == 2) wB = sw1 + (128 + ks * 224) * HD + c0;
        else             wB = sw1 + (576 + ks * 224) * HD + c0;

        const float4* xr0 = reinterpret_cast<const float4*>(sm + (p0 + 0) * XQF + (64 + ks * 224) * 2);
        const float4* xr1 = reinterpret_cast<const float4*>(sm + (p0 + 1) * XQF + (64 + ks * 224) * 2);
        const float4* xr2 = reinterpret_cast<const float4*>(sm + (p0 + 2) * XQF + (64 + ks * 224) * 2);

        #pragma unroll 4
        for (int it = 0; it < 112; it++) {
            float4 w0 = *reinterpret_cast<const float4*>(wB);
            float4 w1 = *reinterpret_cast<const float4*>(wB + HD);
            wB += 2 * HD;
            float4 xa  = xr0[it];
            float4 xb4 = xr1[it];
            float4 xc  = xr2[it];
            PSTEP(acc[0], xa);
            PSTEP(acc[1], xb4);
            PSTEP(acc[2], xc);
        }

        if (m >= 2) {  // emb prefix (64 virtual k-rows)
            const float* wA = sw1 + ((m == 3 ? 64 : 0) + ks * 32) * HD + c0;
            const float4* ar0 = reinterpret_cast<const float4*>(sm + (p0 + 0) * XQF + (ks * 32) * 2);
            const float4* ar1 = reinterpret_cast<const float4*>(sm + (p0 + 1) * XQF + (ks * 32) * 2);
            const float4* ar2 = reinterpret_cast<const float4*>(sm + (p0 + 2) * XQF + (ks * 32) * 2);
            #pragma unroll 4
            for (int it = 0; it < 16; it++) {
                float4 w0 = *reinterpret_cast<const float4*>(wA);
                float4 w1 = *reinterpret_cast<const float4*>(wA + HD);
                wA += 2 * HD;
                float4 xa  = ar0[it];
                float4 xb4 = ar1[it];
                float4 xc  = ar2[it];
                PSTEP(acc[0], xa);
                PSTEP(acc[1], xb4);
                PSTEP(acc[2], xc);
            }
        }

        // reduce ks halves (lane bit 4)
        #pragma unroll
        for (int pp = 0; pp < 3; pp++)
            #pragma unroll
            for (int cc = 0; cc < 4; cc++) {
                unsigned long long v = *reinterpret_cast<unsigned long long*>(&acc[pp][cc]);
                unsigned long long o = __shfl_xor_sync(0xffffffffu, v, 16);
                float2 ov = *reinterpret_cast<float2*>(&o);
                acc[pp][cc].x += ov.x;
                acc[pp][cc].y += ov.y;
            }

        if (ks == 0) {
            float4 bb = make_float4(0.f, 0.f, 0.f, 0.f);
            if (m == 0) bb = *reinterpret_cast<const float4*>(cb1 + c0);
            if (m == 2) bb = *reinterpret_cast<const float4*>(sb1 + c0);
            float bcol[4] = {bb.x, bb.y, bb.z, bb.w};
            const int npp = (rg == 3) ? 2 : 3;
            float* pm = g_proj + ((size_t)m * BB + b) * NN * HD;
            #pragma unroll
            for (int pp = 0; pp < 3; pp++) {
                if (pp < npp) {
                    int r0 = (p0 + pp) * 2;
                    #pragma unroll
                    for (int cc = 0; cc < 4; cc++) {
                        pm[r0 * HD + c0 + cc]       = acc[pp][cc].x + bcol[cc];
                        pm[(r0 + 1) * HD + c0 + cc] = acc[pp][cc].y + bcol[cc];
                    }
                }
            }
        }
    } else {
        // ---- stats + gram half (role-4)*128 .. ----
        float* xs   = sm;
        float* mu   = sm + NN * XSS;
        float* istd = mu + NN;
        const float* xb = x + (size_t)b * NN * FF;
        for (int idx = tid; idx < NN * FF; idx += 128) {
            int i = idx / FF, k = idx - i * FF;
            xs[i * XSS + k] = xb[idx];
        }
        __syncthreads();
        for (int i = warp; i < NN; i += 4) {
            float smv = 0.f, sq = 0.f;
            const float* r = xs + i * XSS;
            for (int k = lane * 4; k < FF; k += 128) {
                float4 v = *reinterpret_cast<const float4*>(r + k);
                smv += v.x + v.y + v.z + v.w;
                sq  += v.x * v.x + v.y * v.y + v.z * v.z + v.w * v.w;
            }
            smv = warpSum(smv); sq = warpSum(sq);
            if (lane == 0) {
                float mm  = smv / FF;
                float var = (sq - FF * mm * mm) / (FF - 1);
                var = fmaxf(var, 0.f);
                mu[i]   = mm;
                istd[i] = 1.0f / (sqrtf(var) + 1e-8f);
            }
        }
        __syncthreads();
        int pi = (role - 4) * 128 + tid;
        if (pi < NUPD) {
            int i = 0, rem = pi;
            while (rem >= NN - i) { rem -= NN - i; i++; }
            int j = i + rem;
            const float* ri = xs + i * XSS;
            const float* rj = xs + j * XSS;
            float dot = 0.f;
            #pragma unroll 4
            for (int k = 0; k < FF; k += 4) {
                float4 a = *reinterpret_cast<const float4*>(ri + k);
                float4 c = *reinterpret_cast<const float4*>(rj + k);
                dot += a.x * c.x + a.y * c.y + a.z * c.z + a.w * c.w;
            }
            float cv = fabsf((dot - (float)FF * mu[i] * mu[j]) * istd[i] * istd[j]) * (1.0f / FF);
            g_corr[b * NPAIR + i * NN + j] = cv;
            g_corr[b * NPAIR + j * NN + i] = cv;
        }
    }
}

// ================= K2: pair MLPs + fusion =================
struct __align__(16) S2 {
    float proj[4][NN * PSTR];
    float sw2s[HD * 36];
    float corrs[NPAIR], gcs[NPAIR], adjs[NPAIR];
    float cw2s[HD], lngs[HD], lnbs[HD], sb2s[32], sw3s[32];
    int   pl[NUP];
};

__global__ __launch_bounds__(512)
void k2(const float* __restrict__ cw2, const float* __restrict__ cb2,
        const float* __restrict__ lng, const float* __restrict__ lnb,
        const float* __restrict__ sw2, const float* __restrict__ sb2,
        const float* __restrict__ sw3, const float* __restrict__ sb3,
        const float* __restrict__ thr, const float* __restrict__ alpha_p,
        float* __restrict__ out) {
    __shared__ S2 s;
    const int b   = blockIdx.x;
    const int tid = threadIdx.x;

    for (int mm = 0; mm < 4; mm++) {
        const float* src = g_proj + ((size_t)mm * BB + b) * NN * HD;
        for (int idx = tid; idx < NN * HD; idx += 512)
            s.proj[mm][(idx >> 6) * PSTR + (idx & 63)] = src[idx];
    }
    for (int idx = tid; idx < HD * 32; idx += 512) {
        int c = idx >> 5, o = idx & 31;
        s.sw2s[c * 36 + o] = sw2[idx];
    }
    for (int idx = tid; idx < NPAIR; idx += 512) {
        s.corrs[idx] = g_corr[b * NPAIR + idx];
        s.adjs[idx]  = 0.f;
    }
    if (tid < HD) { s.cw2s[tid] = cw2[tid]; s.lngs[tid] = lng[tid]; s.lnbs[tid] = lnb[tid]; }
    if (tid >= HD && tid < HD + 32) { s.sb2s[tid - HD] = sb2[tid - HD]; s.sw3s[tid - HD] = sw3[tid - HD]; }
    if (tid < NPAIR) {
        int i = tid / NN, j = tid - i * NN;
        if (i < j) s.pl[i * (2 * NN - 1 - i) / 2 + (j - i - 1)] = (i << 5) | j;
    }
    __syncthreads();

    if (tid < NUP) {
        const float tthr = 1.0f / (1.0f + __expf(-thr[0]));
        int code = s.pl[tid];
        int i = code >> 5, j = code & 31;
        const float* pi = s.proj[2] + i * PSTR;
        const float* qj = s.proj[3] + j * PSTR;
        float sm = 0.f, sq = 0.f;
        #pragma unroll 4
        for (int c = 0; c < HD; c++) {
            float sv = pi[c] + qj[c];
            sm += sv; sq += sv * sv;
        }
        float muv  = sm * (1.0f / HD);
        float var  = sq * (1.0f / HD) - muv * muv;
        float rstd = rsqrtf(var + 1e-5f);
        float2 h2p[16];
        #pragma unroll
        for (int o = 0; o < 16; o++) h2p[o] = make_float2(s.sb2s[2 * o], s.sb2s[2 * o + 1]);
        #pragma unroll 2
        for (int c = 0; c < HD; c++) {
            float sv = pi[c] + qj[c];
            float h1 = fmaxf((sv - muv) * rstd * s.lngs[c] + s.lnbs[c], 0.f);
            float2 h1d = make_float2(h1, h1);
            const float4* wr = reinterpret_cast<const float4*>(s.sw2s + c * 36);
            #pragma unroll
            for (int o4 = 0; o4 < 8; o4++) {
                float4 w = wr[o4];
                fma2(h2p[2 * o4],     h1d, make_float2(w.x, w.y));
                fma2(h2p[2 * o4 + 1], h1d, make_float2(w.z, w.w));
            }
        }
        float z = sb3[0];
        #pragma unroll
        for (int o = 0; o < 16; o++) {
            z += fmaxf(h2p[o].x, 0.f) * s.sw3s[2 * o];
            z += fmaxf(h2p[o].y, 0.f) * s.sw3s[2 * o + 1];
        }
        float ws  = 1.0f / (1.0f + __expf(-z));
        float val = (ws > tthr) ? ws : 0.f;
        s.adjs[i * NN + j] = val;
        s.adjs[j * NN + i] = val;
    } else if (tid >= 256) {
        const float cb2v = cb2[0];
        for (int pidx = tid - 256; pidx < NPAIR; pidx += 256) {
            int i = pidx / NN, j = pidx - i * NN;
            const float* ui = s.proj[0] + i * PSTR;
            const float* vj = s.proj[1] + j * PSTR;
            float z = cb2v;
            #pragma unroll 4
            for (int c = 0; c < HD; c++)
                z += fmaxf(ui[c] + vj[c], 0.f) * s.cw2s[c];
            float wc = 1.0f / (1.0f + __expf(-z));
            s.gcs[pidx] = s.corrs[pidx] * wc;
        }
    }
    __syncthreads();

    if (tid < NPAIR) {
        const float alpha = 1.0f / (1.0f + __expf(-alpha_p[0]));
        int i = tid / NN, j = tid - i * NN;
        float eye = (i == j) ? 1.0f : 0.0f;
        out[(size_t)b * NPAIR + tid] = alpha * s.gcs[tid] + (1.0f - alpha) * s.adjs[tid] + eye;
    }
}

extern "C" void kernel_launch(void* const* d_in, const int* in_sizes, int n_in,
                              void* d_out, int out_size) {
    const float* x       = (const float*)d_in[0];
    const float* cw1     = (const float*)d_in[1];
    const float* cb1     = (const float*)d_in[2];
    const float* cw2     = (const float*)d_in[3];
    const float* cb2     = (const float*)d_in[4];
    const float* emb     = (const float*)d_in[5];
    const float* sw1     = (const float*)d_in[6];
    const float* sb1     = (const float*)d_in[7];
    const float* ln_g    = (const float*)d_in[8];
    const float* ln_b    = (const float*)d_in[9];
    const float* sw2     = (const float*)d_in[10];
    const float* sb2     = (const float*)d_in[11];
    const float* sw3     = (const float*)d_in[12];
    const float* sb3     = (const float*)d_in[13];
    const float* thr     = (const float*)d_in[14];
    const float* alpha_p = (const float*)d_in[15];
    float* out = (float*)d_out;

    const int k1_smem = 12 * XQF * sizeof(float);  // 49536 B
    static bool attr_set = false;
    if (!attr_set) {
        cudaFuncSetAttribute(k1, cudaFuncAttributeMaxDynamicSharedMemorySize, k1_smem);
        attr_set = true;
    }
    dim3 g1(6, BB);
    k1<<<g1, 128, k1_smem>>>(x, cw1, cb1, emb, sw1, sb1);
    k2<<<BB, 512>>>(cw2, cb2, ln_g, ln_b, sw2, sb2, sw3, sb3, thr, alpha_p, out);
}